// round 5
// baseline (speedup 1.0000x reference)
#include <cuda_runtime.h>
#include <cuda_bf16.h>
#include <cstdint>

// Problem constants
#define BB 4
#define VV 256
#define HH 128
constexpr int ROWS_H = BB * VV;           // 1024
constexpr int ROWS_E = BB * VV * VV;      // 262144
constexpr int TM     = 128;               // e-rows per block in k_main
constexpr int NBLK2  = ROWS_E / TM;       // 2048
constexpr float EPS  = 1e-5f;

// Scratch
__device__ float g_enew[(size_t)ROWS_E * HH];   // 134 MB
__device__ float g_lin[4 * ROWS_H * HH];        // Uh,Vh,Ah,Bh
__device__ float g_statS[HH * NBLK2];
__device__ float g_statQ[HH * NBLK2];
__device__ float g_aggp[HH * NBLK2];
__device__ float g_hnew[ROWS_H * HH];
__device__ float g_scaleE[HH];
__device__ float g_shiftE[HH];

// ---------------- smem geometry for k_main ----------------
constexpr int LDAB   = 136;                 // bf16 elems per tile row (272 B, pad for ldmatrix)
constexpr int TILE_B = 128 * LDAB * 2;      // 34816 B per bf16 tile
constexpr int SM_C2  = 0;                   // 128 floats
constexpr int SM_AHI = 1024;
constexpr int SM_ALO = SM_AHI + TILE_B;     // 35840
constexpr int SM_BHI = SM_ALO + TILE_B;     // 70656
constexpr int SM_BLO = SM_BHI + TILE_B;     // 105472
constexpr int SM_TOTAL = SM_BLO + TILE_B;   // 140288
// post-MMA aliases
constexpr int SM_DS  = 1024;                // 128 x 132 f32 = 67584 B (aliases A tiles)
constexpr int LDS_DS = 132;                 // EVEN: float2 stores stay 8B-aligned
constexpr int SM_RED = SM_BLO;              // 3 * 2 * 128 floats (aliases B lo tile)

__device__ __forceinline__ uint32_t smem_u32(const void* p) {
    uint32_t a;
    asm("{ .reg .u64 t; cvta.to.shared.u64 t, %1; cvt.u32.u64 %0, t; }" : "=r"(a) : "l"(p));
    return a;
}
__device__ __forceinline__ void ldmatrix_x4(uint32_t& r0, uint32_t& r1, uint32_t& r2, uint32_t& r3, uint32_t addr) {
    asm volatile("ldmatrix.sync.aligned.m8n8.x4.shared.b16 {%0,%1,%2,%3}, [%4];"
        : "=r"(r0), "=r"(r1), "=r"(r2), "=r"(r3) : "r"(addr));
}
__device__ __forceinline__ void mma16816(float (&d)[4], const uint32_t (&a)[4], uint32_t b0, uint32_t b1) {
    asm volatile("mma.sync.aligned.m16n8k16.row.col.f32.bf16.bf16.f32 "
        "{%0,%1,%2,%3}, {%4,%5,%6,%7}, {%8,%9}, {%0,%1,%2,%3};"
        : "+f"(d[0]), "+f"(d[1]), "+f"(d[2]), "+f"(d[3])
        : "r"(a[0]), "r"(a[1]), "r"(a[2]), "r"(a[3]), "r"(b0), "r"(b1));
}

__device__ __forceinline__ void cvt_store4(float4 v, char* smem, uint32_t hiOff, uint32_t loOff) {
    __nv_bfloat16 h0 = __float2bfloat16(v.x), h1 = __float2bfloat16(v.y);
    __nv_bfloat16 h2 = __float2bfloat16(v.z), h3 = __float2bfloat16(v.w);
    float r0 = v.x - __bfloat162float(h0), r1 = v.y - __bfloat162float(h1);
    float r2 = v.z - __bfloat162float(h2), r3 = v.w - __bfloat162float(h3);
    __nv_bfloat16 l0 = __float2bfloat16(r0), l1 = __float2bfloat16(r1);
    __nv_bfloat16 l2 = __float2bfloat16(r2), l3 = __float2bfloat16(r3);
    uint2 uh, ul;
    uh.x = ((uint32_t)__bfloat16_as_ushort(h1) << 16) | __bfloat16_as_ushort(h0);
    uh.y = ((uint32_t)__bfloat16_as_ushort(h3) << 16) | __bfloat16_as_ushort(h2);
    ul.x = ((uint32_t)__bfloat16_as_ushort(l1) << 16) | __bfloat16_as_ushort(l0);
    ul.y = ((uint32_t)__bfloat16_as_ushort(l3) << 16) | __bfloat16_as_ushort(l2);
    *(uint2*)(smem + hiOff) = uh;
    *(uint2*)(smem + loOff) = ul;
}

// ---------------- K1: HMMA Ce GEMM + e_new + gates + agg + stats ----------------
__global__ void __launch_bounds__(256, 1)
k_main(const float* __restrict__ e,
       const float* __restrict__ Cw, const float* __restrict__ Cb) {
    extern __shared__ char sm[];
    uint32_t smb = smem_u32(sm);
    int tid = threadIdx.x;
    int wid = tid >> 5, lane = tid & 31;

    int blk = blockIdx.x;
    int rbase = blk * TM;
    int bi = blk >> 1;            // b*V + i
    int b  = bi >> 8;
    int j0 = (blk & 1) * TM;      // j range start

    // c2 = Cb + Bh[bi]
    if (tid < HH)
        ((float*)(sm + SM_C2))[tid] = Cb[tid] + g_lin[(size_t)3 * ROWS_H * HH + (size_t)bi * HH + tid];

    // Convert e tile (A) and Cw (B) to bf16 hi/lo, padded rows (272 B)
    const float4* esrc = (const float4*)(e + (size_t)rbase * HH);
    const float4* wsrc = (const float4*)Cw;
    for (int idx = tid; idx < 128 * 32; idx += 256) {
        int row = idx >> 5, c4 = idx & 31;
        uint32_t off = (uint32_t)row * (LDAB * 2) + c4 * 8;
        cvt_store4(esrc[idx], sm, SM_AHI + off, SM_ALO + off);
        cvt_store4(wsrc[idx], sm, SM_BHI + off, SM_BLO + off);
    }
    __syncthreads();

    // warp grid: 4 (row blocks of 32) x 2 (col halves of 64)
    int wm = wid >> 1, wn = wid & 1;
    float d[2][8][4];
#pragma unroll
    for (int mt = 0; mt < 2; mt++)
#pragma unroll
        for (int nt = 0; nt < 8; nt++)
#pragma unroll
            for (int q = 0; q < 4; q++) d[mt][nt][q] = 0.f;

    // per-lane ldmatrix address components (byte offsets)
    uint32_t aLaneOff = (uint32_t)(wm * 32 + (lane & 15)) * (LDAB * 2) + ((lane >> 4) * 8) * 2;
    uint32_t bLaneOff = (uint32_t)(wn * 64 + (((lane >> 4) & 1) * 8) + (lane & 7)) * (LDAB * 2)
                      + (((lane >> 3) & 1) * 8) * 2;

#pragma unroll
    for (int p = 0; p < 3; p++) {
        uint32_t aBase = smb + ((p == 2) ? SM_ALO : SM_AHI) + aLaneOff;
        uint32_t bBase = smb + ((p == 1) ? SM_BLO : SM_BHI) + bLaneOff;
#pragma unroll
        for (int kk = 0; kk < 8; kk++) {
            uint32_t a0[4], a1[4];
            ldmatrix_x4(a0[0], a0[1], a0[2], a0[3], aBase + kk * 32);
            ldmatrix_x4(a1[0], a1[1], a1[2], a1[3], aBase + kk * 32 + 16 * (LDAB * 2));
            uint32_t bb[16];
#pragma unroll
            for (int q = 0; q < 4; q++)
                ldmatrix_x4(bb[q * 4], bb[q * 4 + 1], bb[q * 4 + 2], bb[q * 4 + 3],
                            bBase + kk * 32 + (uint32_t)q * 16 * (LDAB * 2));
#pragma unroll
            for (int nt = 0; nt < 8; nt++) {
                uint32_t b0 = bb[(nt >> 1) * 4 + (nt & 1) * 2];
                uint32_t b1 = bb[(nt >> 1) * 4 + (nt & 1) * 2 + 1];
                mma16816(d[0][nt], a0, b0, b1);
                mma16816(d[1][nt], a1, b0, b1);
            }
        }
    }
    __syncthreads();   // done reading A/B tiles; alias as Ds

    // scatter accumulators into f32 tile Ds[128][132]
    float* Ds = (float*)(sm + SM_DS);
    {
        int g = lane >> 2, t2 = (lane & 3) * 2;
#pragma unroll
        for (int mt = 0; mt < 2; mt++) {
            int r0 = wm * 32 + mt * 16 + g;
#pragma unroll
            for (int nt = 0; nt < 8; nt++) {
                int c = wn * 64 + nt * 8 + t2;
                *(float2*)&Ds[r0 * LDS_DS + c]       = make_float2(d[mt][nt][0], d[mt][nt][1]);
                *(float2*)&Ds[(r0 + 8) * LDS_DS + c] = make_float2(d[mt][nt][2], d[mt][nt][3]);
            }
        }
    }
    __syncthreads();

    // column-wise epilogue: thread = (column n, row half)
    {
        int n = tid & 127;
        int rh = tid >> 7;           // 0 or 1 -> rows rh*64 .. +63
        float c2v = ((const float*)(sm + SM_C2))[n];
        const float* ah = g_lin + (size_t)2 * ROWS_H * HH + (size_t)(b * VV + j0 + rh * 64) * HH + n;
        const float* vh = g_lin + (size_t)1 * ROWS_H * HH + (size_t)(b * VV + j0 + rh * 64) * HH + n;
        float* dst = g_enew + (size_t)(rbase + rh * 64) * HH + n;
        const float* dsp = Ds + (rh * 64) * LDS_DS + n;

        float sS = 0.f, sQ = 0.f, sA = 0.f;
#pragma unroll 8
        for (int r = 0; r < 64; r++) {
            float x = dsp[r * LDS_DS] + c2v + ah[(size_t)r * HH];
            dst[(size_t)r * HH] = x;
            sS += x;
            sQ = fmaf(x, x, sQ);
            float gte = 1.f / (1.f + __expf(-x));
            sA = fmaf(gte, vh[(size_t)r * HH], sA);
        }
        float* redS = (float*)(sm + SM_RED);
        float* redQ = redS + 256;
        float* redA = redQ + 256;
        redS[rh * 128 + n] = sS;
        redQ[rh * 128 + n] = sQ;
        redA[rh * 128 + n] = sA;
    }
    __syncthreads();
    if (tid < HH) {
        float* redS = (float*)(sm + SM_RED);
        float* redQ = redS + 256;
        float* redA = redQ + 256;
        g_statS[(size_t)tid * NBLK2 + blk] = redS[tid] + redS[128 + tid];
        g_statQ[(size_t)tid * NBLK2 + blk] = redQ[tid] + redQ[128 + tid];
        g_aggp[(size_t)tid * NBLK2 + blk]  = redA[tid] + redA[128 + tid];
    }
}

// ---------------- K0: the four small linears on h (fp32, exact) ----------------
constexpr int WS_STRIDE = 132;
constexpr int SMEM_LIN = (HH * WS_STRIDE + 64 * HH) * 4;

__device__ __forceinline__ void fma2(unsigned long long& d, unsigned long long a, unsigned long long b) {
    asm("fma.rn.f32x2 %0, %1, %2, %0;" : "+l"(d) : "l"(a), "l"(b));
}
__device__ __forceinline__ float2 unpack2(unsigned long long v) {
    float2 r; asm("mov.b64 {%0,%1}, %2;" : "=f"(r.x), "=f"(r.y) : "l"(v)); return r;
}

__global__ void k_lin(const float* __restrict__ h,
                      const float* __restrict__ W0, const float* __restrict__ b0,
                      const float* __restrict__ W1, const float* __restrict__ b1,
                      const float* __restrict__ W2, const float* __restrict__ b2,
                      const float* __restrict__ W3, const float* __restrict__ b3) {
    extern __shared__ float smf[];
    float* Ws = smf;
    float* As = Ws + HH * WS_STRIDE;

    int m = blockIdx.y;
    const float* W    = (m == 0) ? W0 : (m == 1) ? W1 : (m == 2) ? W2 : W3;
    const float* bias = (m == 0) ? b0 : (m == 1) ? b1 : (m == 2) ? b2 : b3;

    int tid = threadIdx.x;
    for (int i = tid; i < HH * 32; i += 256) {
        int n = i >> 5, kc = i & 31;
        *(float4*)&Ws[n * WS_STRIDE + kc * 4] = *(const float4*)&W[n * HH + kc * 4];
    }
    int r0 = blockIdx.x * 64;
    const float4* hsrc = (const float4*)(h + (size_t)r0 * HH);
    for (int i = tid; i < 64 * 32; i += 256) ((float4*)As)[i] = hsrc[i];
    __syncthreads();

    int tr = tid >> 5, tc = tid & 31;
    int jj0 = tr * 8;
    unsigned long long acc[8][4];
#pragma unroll
    for (int jl = 0; jl < 8; jl++)
#pragma unroll
        for (int mm = 0; mm < 4; mm++) acc[jl][mm] = 0ull;
#pragma unroll 4
    for (int k = 0; k < HH; k += 4) {
        ulonglong2 w0 = *(const ulonglong2*)&Ws[(tc +  0) * WS_STRIDE + k];
        ulonglong2 w1 = *(const ulonglong2*)&Ws[(tc + 32) * WS_STRIDE + k];
        ulonglong2 w2 = *(const ulonglong2*)&Ws[(tc + 64) * WS_STRIDE + k];
        ulonglong2 w3 = *(const ulonglong2*)&Ws[(tc + 96) * WS_STRIDE + k];
#pragma unroll
        for (int jl = 0; jl < 8; jl++) {
            ulonglong2 a = *(const ulonglong2*)&As[(jj0 + jl) * HH + k];
            fma2(acc[jl][0], a.x, w0.x); fma2(acc[jl][0], a.y, w0.y);
            fma2(acc[jl][1], a.x, w1.x); fma2(acc[jl][1], a.y, w1.y);
            fma2(acc[jl][2], a.x, w2.x); fma2(acc[jl][2], a.y, w2.y);
            fma2(acc[jl][3], a.x, w3.x); fma2(acc[jl][3], a.y, w3.y);
        }
    }
    float bv[4];
#pragma unroll
    for (int mm = 0; mm < 4; mm++) bv[mm] = bias[tc + 32 * mm];
    float* dst = g_lin + (size_t)m * ROWS_H * HH;
#pragma unroll
    for (int jl = 0; jl < 8; jl++) {
        size_t row = (size_t)(r0 + jj0 + jl) * HH;
#pragma unroll
        for (int mm = 0; mm < 4; mm++) {
            float2 p = unpack2(acc[jl][mm]);
            dst[row + tc + 32 * mm] = p.x + p.y + bv[mm];
        }
    }
}

// ---------------- K2: stats reduce (fp64) + h path + h_out ----------------
__device__ __forceinline__ double blk_red(double v, double* sb) {
    int tid = threadIdx.x;
    sb[tid] = v; __syncthreads();
    for (int o = 128; o > 0; o >>= 1) {
        if (tid < o) sb[tid] += sb[tid + o];
        __syncthreads();
    }
    double r = sb[0]; __syncthreads();
    return r;
}

__global__ void k_finalize(const float* __restrict__ h_in,
                           const float* __restrict__ gamma_h, const float* __restrict__ beta_h,
                           const float* __restrict__ gamma_e, const float* __restrict__ beta_e,
                           float* __restrict__ out_h) {
    __shared__ double sb[256];
    __shared__ float sbroad[2];
    int n = blockIdx.x;
    int tid = threadIdx.x;

    double s = 0.0, q = 0.0;
    for (int p = tid; p < NBLK2; p += 256) {
        s += (double)g_statS[(size_t)n * NBLK2 + p];
        q += (double)g_statQ[(size_t)n * NBLK2 + p];
    }
    s = blk_red(s, sb);
    q = blk_red(q, sb);
    if (tid == 0) {
        double mean = s / (double)ROWS_E;
        double var  = q / (double)ROWS_E - mean * mean;
        float rstd  = (float)(1.0 / sqrt(var + (double)EPS));
        float sc    = gamma_e[n] * rstd;
        g_scaleE[n] = sc;
        g_shiftE[n] = beta_e[n] - (float)mean * sc;
    }

    double hs = 0.0, hq = 0.0;
    for (int r = tid; r < ROWS_H; r += 256) {
        const float* ap = &g_aggp[(size_t)n * NBLK2 + r * 2];
        float agg = ap[0] + ap[1];
        float hn  = g_lin[(size_t)r * HH + n] + agg;  // Uh + agg
        g_hnew[(size_t)r * HH + n] = hn;
        hs += (double)hn; hq += (double)hn * (double)hn;
    }
    hs = blk_red(hs, sb);
    hq = blk_red(hq, sb);
    if (tid == 0) {
        double mean = hs / (double)ROWS_H;
        double var  = hq / (double)ROWS_H - mean * mean;
        float rstd  = (float)(1.0 / sqrt(var + (double)EPS));
        float sc    = gamma_h[n] * rstd;
        sbroad[0]   = sc;
        sbroad[1]   = beta_h[n] - (float)mean * sc;
    }
    __syncthreads();
    float sc = sbroad[0], sh = sbroad[1];
    for (int r = tid; r < ROWS_H; r += 256) {
        float v = fmaf(g_hnew[(size_t)r * HH + n], sc, sh);
        out_h[(size_t)r * HH + n] = h_in[(size_t)r * HH + n] + fmaxf(v, 0.f);
    }
}

// ---------------- K3: e epilogue ----------------
__global__ void k_epi(const float* __restrict__ e_in, float* __restrict__ out_e) {
    int tid = threadIdx.x;
    const float4* en4 = (const float4*)g_enew;
    const float4* ei4 = (const float4*)e_in;
    const float4* sc4 = (const float4*)g_scaleE;
    const float4* sh4 = (const float4*)g_shiftE;
    float4* out4 = (float4*)out_e;
#pragma unroll
    for (int it = 0; it < 4; it++) {
        size_t f = (size_t)blockIdx.x * 1024 + it * 256 + tid;
        int c = (int)(f & 31);
        float4 sc = __ldg(&sc4[c]);
        float4 sh = __ldg(&sh4[c]);
        float4 x  = en4[f];
        float4 ei = ei4[f];
        float4 o;
        o.x = ei.x + fmaxf(fmaf(x.x, sc.x, sh.x), 0.f);
        o.y = ei.y + fmaxf(fmaf(x.y, sc.y, sh.y), 0.f);
        o.z = ei.z + fmaxf(fmaf(x.z, sc.z, sh.z), 0.f);
        o.w = ei.w + fmaxf(fmaf(x.w, sc.w, sh.w), 0.f);
        out4[f] = o;
    }
}

extern "C" void kernel_launch(void* const* d_in, const int* in_sizes, int n_in,
                              void* d_out, int out_size) {
    (void)in_sizes; (void)n_in; (void)out_size;
    const float* h  = (const float*)d_in[0];
    const float* e  = (const float*)d_in[1];
    const float* Uw = (const float*)d_in[3];
    const float* Ub = (const float*)d_in[4];
    const float* Vw = (const float*)d_in[5];
    const float* Vb = (const float*)d_in[6];
    const float* Aw = (const float*)d_in[7];
    const float* Ab = (const float*)d_in[8];
    const float* Bw = (const float*)d_in[9];
    const float* Bb = (const float*)d_in[10];
    const float* Cw = (const float*)d_in[11];
    const float* Cb = (const float*)d_in[12];
    const float* gh = (const float*)d_in[13];
    const float* bh = (const float*)d_in[14];
    const float* ge = (const float*)d_in[15];
    const float* be = (const float*)d_in[16];
    float* out = (float*)d_out;   // [h_out (131072) | e_out (33554432)]

    cudaFuncSetAttribute(k_lin,  cudaFuncAttributeMaxDynamicSharedMemorySize, SMEM_LIN);
    cudaFuncSetAttribute(k_main, cudaFuncAttributeMaxDynamicSharedMemorySize, SM_TOTAL);

    k_lin<<<dim3(ROWS_H / 64, 4), 256, SMEM_LIN>>>(h, Uw, Ub, Vw, Vb, Aw, Ab, Bw, Bb);
    k_main<<<NBLK2, 256, SM_TOTAL>>>(e, Cw, Cb);
    k_finalize<<<HH, 256>>>(h, gh, bh, ge, be, out);
    k_epi<<<ROWS_E * HH / 4096, 256>>>(e, out + ROWS_H * HH);
}

// round 10
// speedup vs baseline: 1.5728x; 1.5728x over previous
#include <cuda_runtime.h>
#include <cuda_bf16.h>
#include <cstdint>

// Problem constants
#define BB 4
#define VV 256
#define HH 128
constexpr int ROWS_H = BB * VV;           // 1024
constexpr int ROWS_E = BB * VV * VV;      // 262144
constexpr int TM     = 128;               // e-rows per block in k_main
constexpr int NBLK2  = ROWS_E / TM;       // 2048
constexpr float EPS  = 1e-5f;

// Scratch
__device__ float g_enew[(size_t)ROWS_E * HH];   // 134 MB
__device__ float g_lin[4 * ROWS_H * HH];        // Uh,Vh,Ah,Bh
__device__ float g_statS[HH * NBLK2];
__device__ float g_statQ[HH * NBLK2];
__device__ float g_aggp[HH * NBLK2];
__device__ float g_hnew[ROWS_H * HH];
__device__ float g_scaleE[HH];
__device__ float g_shiftE[HH];

// ---------------- smem geometry for k_main (K chunked: 2 x 64) ----------------
constexpr int LDC    = 72;                  // bf16 elems per tile row (144 B; 9 units, odd)
constexpr int TILE_B = 128 * LDC * 2;       // 18432 B per bf16 tile (128 rows x 64 cols)
constexpr int SM_C2  = 0;                   // 128 floats
constexpr int SM_AHI = 1024;
constexpr int SM_ALO = SM_AHI + TILE_B;     // 19456
constexpr int SM_BHI = SM_ALO + TILE_B;     // 37888
constexpr int SM_BLO = SM_BHI + TILE_B;     // 56320
constexpr int SM_RED = SM_BLO + TILE_B;     // 74752 (3*256 floats, persistent)
constexpr int SM_TOTAL = SM_RED + 3072;     // 77824 -> 2 CTAs/SM
// post-MMA alias: Ds 128 x 132 f32 = 67584 B starting at 1024 (ends 68608 < SM_RED)
constexpr int SM_DS  = 1024;
constexpr int LDS_DS = 132;                 // even: float2 stores stay 8B-aligned

__device__ __forceinline__ uint32_t smem_u32(const void* p) {
    uint32_t a;
    asm("{ .reg .u64 t; cvta.to.shared.u64 t, %1; cvt.u32.u64 %0, t; }" : "=r"(a) : "l"(p));
    return a;
}
// volatile + memory clobber: smem contents change between chunks at the SAME
// addresses — without this the compiler CSEs chunk-2 loads to chunk-1 fragments.
__device__ __forceinline__ void ldmatrix_x4(uint32_t& r0, uint32_t& r1, uint32_t& r2, uint32_t& r3, uint32_t addr) {
    asm volatile("ldmatrix.sync.aligned.m8n8.x4.shared.b16 {%0,%1,%2,%3}, [%4];"
        : "=r"(r0), "=r"(r1), "=r"(r2), "=r"(r3) : "r"(addr) : "memory");
}
__device__ __forceinline__ void mma16816(float (&d)[4], const uint32_t (&a)[4], uint32_t b0, uint32_t b1) {
    asm("mma.sync.aligned.m16n8k16.row.col.f32.bf16.bf16.f32 "
        "{%0,%1,%2,%3}, {%4,%5,%6,%7}, {%8,%9}, {%0,%1,%2,%3};"
        : "+f"(d[0]), "+f"(d[1]), "+f"(d[2]), "+f"(d[3])
        : "r"(a[0]), "r"(a[1]), "r"(a[2]), "r"(a[3]), "r"(b0), "r"(b1));
}

__device__ __forceinline__ void cvt_store4(float4 v, char* smem, uint32_t hiOff, uint32_t loOff) {
    __nv_bfloat16 h0 = __float2bfloat16(v.x), h1 = __float2bfloat16(v.y);
    __nv_bfloat16 h2 = __float2bfloat16(v.z), h3 = __float2bfloat16(v.w);
    float r0 = v.x - __bfloat162float(h0), r1 = v.y - __bfloat162float(h1);
    float r2 = v.z - __bfloat162float(h2), r3 = v.w - __bfloat162float(h3);
    __nv_bfloat16 l0 = __float2bfloat16(r0), l1 = __float2bfloat16(r1);
    __nv_bfloat16 l2 = __float2bfloat16(r2), l3 = __float2bfloat16(r3);
    uint2 uh, ul;
    uh.x = ((uint32_t)__bfloat16_as_ushort(h1) << 16) | __bfloat16_as_ushort(h0);
    uh.y = ((uint32_t)__bfloat16_as_ushort(h3) << 16) | __bfloat16_as_ushort(h2);
    ul.x = ((uint32_t)__bfloat16_as_ushort(l1) << 16) | __bfloat16_as_ushort(l0);
    ul.y = ((uint32_t)__bfloat16_as_ushort(l3) << 16) | __bfloat16_as_ushort(l2);
    *(uint2*)(smem + hiOff) = uh;
    *(uint2*)(smem + loOff) = ul;
}

// ---------------- K1: HMMA Ce GEMM + e_new + gates + agg + stats ----------------
__global__ void __launch_bounds__(256, 2)
k_main(const float* __restrict__ e,
       const float* __restrict__ Cw, const float* __restrict__ Cb) {
    extern __shared__ char sm[];
    uint32_t smb = smem_u32(sm);
    int tid = threadIdx.x;
    int wid = tid >> 5, lane = tid & 31;

    int blk = blockIdx.x;
    int rbase = blk * TM;
    int bi = blk >> 1;            // b*V + i
    int b  = bi >> 8;
    int j0 = (blk & 1) * TM;      // j range start

    // c2 = Cb + Bh[bi]
    if (tid < HH)
        ((float*)(sm + SM_C2))[tid] = Cb[tid] + g_lin[(size_t)3 * ROWS_H * HH + (size_t)bi * HH + tid];

    // warp grid: 4 (row blocks of 32) x 2 (col halves of 64)
    int wm = wid >> 1, wn = wid & 1;
    float d[2][8][4];
#pragma unroll
    for (int mt = 0; mt < 2; mt++)
#pragma unroll
        for (int nt = 0; nt < 8; nt++)
#pragma unroll
            for (int q = 0; q < 4; q++) d[mt][nt][q] = 0.f;

    // per-lane ldmatrix address components (byte offsets, row stride 144 B)
    uint32_t aLaneOff = (uint32_t)(wm * 32 + (lane & 15)) * (LDC * 2) + (lane >> 4) * 16;
    uint32_t bLaneOff = (uint32_t)(wn * 64 + (((lane >> 4) & 1) * 8) + (lane & 7)) * (LDC * 2)
                      + ((lane >> 3) & 1) * 16;

#pragma unroll
    for (int ch = 0; ch < 2; ch++) {
        // load + convert this K-chunk (cols ch*64 .. +63) of e tile and Cw
        const float* eb = e + (size_t)rbase * HH + ch * 64;
        const float* wb = Cw + ch * 64;
        for (int idx = tid; idx < 128 * 16; idx += 256) {
            int row = idx >> 4, c4 = idx & 15;
            uint32_t off = (uint32_t)row * (LDC * 2) + c4 * 8;
            float4 ev = *(const float4*)&eb[(size_t)row * HH + c4 * 4];
            float4 wv = *(const float4*)&wb[(size_t)row * HH + c4 * 4];
            cvt_store4(ev, sm, SM_AHI + off, SM_ALO + off);
            cvt_store4(wv, sm, SM_BHI + off, SM_BLO + off);
        }
        __syncthreads();

#pragma unroll
        for (int p = 0; p < 3; p++) {
            uint32_t aBase = smb + ((p == 2) ? SM_ALO : SM_AHI) + aLaneOff;
            uint32_t bBase = smb + ((p == 1) ? SM_BLO : SM_BHI) + bLaneOff;
#pragma unroll
            for (int kk = 0; kk < 4; kk++) {
                uint32_t a0[4], a1[4];
                ldmatrix_x4(a0[0], a0[1], a0[2], a0[3], aBase + kk * 32);
                ldmatrix_x4(a1[0], a1[1], a1[2], a1[3], aBase + kk * 32 + 16 * (LDC * 2));
                uint32_t bb[16];
#pragma unroll
                for (int q = 0; q < 4; q++)
                    ldmatrix_x4(bb[q * 4], bb[q * 4 + 1], bb[q * 4 + 2], bb[q * 4 + 3],
                                bBase + kk * 32 + (uint32_t)q * 16 * (LDC * 2));
#pragma unroll
                for (int nt = 0; nt < 8; nt++) {
                    uint32_t b0 = bb[(nt >> 1) * 4 + (nt & 1) * 2];
                    uint32_t b1 = bb[(nt >> 1) * 4 + (nt & 1) * 2 + 1];
                    mma16816(d[0][nt], a0, b0, b1);
                    mma16816(d[1][nt], a1, b0, b1);
                }
            }
        }
        __syncthreads();   // tiles consumed; next chunk (or Ds alias) may overwrite
    }

    // scatter accumulators into f32 tile Ds[128][132]
    float* Ds = (float*)(sm + SM_DS);
    {
        int g = lane >> 2, t2 = (lane & 3) * 2;
#pragma unroll
        for (int mt = 0; mt < 2; mt++) {
            int r0 = wm * 32 + mt * 16 + g;
#pragma unroll
            for (int nt = 0; nt < 8; nt++) {
                int c = wn * 64 + nt * 8 + t2;
                *(float2*)&Ds[r0 * LDS_DS + c]       = make_float2(d[mt][nt][0], d[mt][nt][1]);
                *(float2*)&Ds[(r0 + 8) * LDS_DS + c] = make_float2(d[mt][nt][2], d[mt][nt][3]);
            }
        }
    }
    __syncthreads();

    // column-wise epilogue: thread = (column n, row half)
    {
        int n = tid & 127;
        int rh = tid >> 7;           // 0 or 1 -> rows rh*64 .. +63
        float c2v = ((const float*)(sm + SM_C2))[n];
        const float* ah = g_lin + (size_t)2 * ROWS_H * HH + (size_t)(b * VV + j0 + rh * 64) * HH + n;
        const float* vh = g_lin + (size_t)1 * ROWS_H * HH + (size_t)(b * VV + j0 + rh * 64) * HH + n;
        float* dst = g_enew + (size_t)(rbase + rh * 64) * HH + n;
        const float* dsp = Ds + (rh * 64) * LDS_DS + n;

        float sS = 0.f, sQ = 0.f, sA = 0.f;
#pragma unroll 8
        for (int r = 0; r < 64; r++) {
            float x = dsp[r * LDS_DS] + c2v + ah[(size_t)r * HH];
            dst[(size_t)r * HH] = x;
            sS += x;
            sQ = fmaf(x, x, sQ);
            float gte = 1.f / (1.f + __expf(-x));
            sA = fmaf(gte, vh[(size_t)r * HH], sA);
        }
        float* redS = (float*)(sm + SM_RED);
        float* redQ = redS + 256;
        float* redA = redQ + 256;
        redS[rh * 128 + n] = sS;
        redQ[rh * 128 + n] = sQ;
        redA[rh * 128 + n] = sA;
    }
    __syncthreads();
    if (tid < HH) {
        float* redS = (float*)(sm + SM_RED);
        float* redQ = redS + 256;
        float* redA = redQ + 256;
        g_statS[(size_t)tid * NBLK2 + blk] = redS[tid] + redS[128 + tid];
        g_statQ[(size_t)tid * NBLK2 + blk] = redQ[tid] + redQ[128 + tid];
        g_aggp[(size_t)tid * NBLK2 + blk]  = redA[tid] + redA[128 + tid];
    }
}

// ---------------- K0: the four small linears on h (fp32, exact) ----------------
constexpr int WS_STRIDE = 132;
constexpr int SMEM_LIN = (HH * WS_STRIDE + 64 * HH) * 4;

__device__ __forceinline__ void fma2(unsigned long long& d, unsigned long long a, unsigned long long b) {
    asm("fma.rn.f32x2 %0, %1, %2, %0;" : "+l"(d) : "l"(a), "l"(b));
}
__device__ __forceinline__ float2 unpack2(unsigned long long v) {
    float2 r; asm("mov.b64 {%0,%1}, %2;" : "=f"(r.x), "=f"(r.y) : "l"(v)); return r;
}

__global__ void k_lin(const float* __restrict__ h,
                      const float* __restrict__ W0, const float* __restrict__ b0,
                      const float* __restrict__ W1, const float* __restrict__ b1,
                      const float* __restrict__ W2, const float* __restrict__ b2,
                      const float* __restrict__ W3, const float* __restrict__ b3) {
    extern __shared__ float smf[];
    float* Ws = smf;
    float* As = Ws + HH * WS_STRIDE;

    int m = blockIdx.y;
    const float* W    = (m == 0) ? W0 : (m == 1) ? W1 : (m == 2) ? W2 : W3;
    const float* bias = (m == 0) ? b0 : (m == 1) ? b1 : (m == 2) ? b2 : b3;

    int tid = threadIdx.x;
    for (int i = tid; i < HH * 32; i += 256) {
        int n = i >> 5, kc = i & 31;
        *(float4*)&Ws[n * WS_STRIDE + kc * 4] = *(const float4*)&W[n * HH + kc * 4];
    }
    int r0 = blockIdx.x * 64;
    const float4* hsrc = (const float4*)(h + (size_t)r0 * HH);
    for (int i = tid; i < 64 * 32; i += 256) ((float4*)As)[i] = hsrc[i];
    __syncthreads();

    int tr = tid >> 5, tc = tid & 31;
    int jj0 = tr * 8;
    unsigned long long acc[8][4];
#pragma unroll
    for (int jl = 0; jl < 8; jl++)
#pragma unroll
        for (int mm = 0; mm < 4; mm++) acc[jl][mm] = 0ull;
#pragma unroll 4
    for (int k = 0; k < HH; k += 4) {
        ulonglong2 w0 = *(const ulonglong2*)&Ws[(tc +  0) * WS_STRIDE + k];
        ulonglong2 w1 = *(const ulonglong2*)&Ws[(tc + 32) * WS_STRIDE + k];
        ulonglong2 w2 = *(const ulonglong2*)&Ws[(tc + 64) * WS_STRIDE + k];
        ulonglong2 w3 = *(const ulonglong2*)&Ws[(tc + 96) * WS_STRIDE + k];
#pragma unroll
        for (int jl = 0; jl < 8; jl++) {
            ulonglong2 a = *(const ulonglong2*)&As[(jj0 + jl) * HH + k];
            fma2(acc[jl][0], a.x, w0.x); fma2(acc[jl][0], a.y, w0.y);
            fma2(acc[jl][1], a.x, w1.x); fma2(acc[jl][1], a.y, w1.y);
            fma2(acc[jl][2], a.x, w2.x); fma2(acc[jl][2], a.y, w2.y);
            fma2(acc[jl][3], a.x, w3.x); fma2(acc[jl][3], a.y, w3.y);
        }
    }
    float bv[4];
#pragma unroll
    for (int mm = 0; mm < 4; mm++) bv[mm] = bias[tc + 32 * mm];
    float* dst = g_lin + (size_t)m * ROWS_H * HH;
#pragma unroll
    for (int jl = 0; jl < 8; jl++) {
        size_t row = (size_t)(r0 + jj0 + jl) * HH;
#pragma unroll
        for (int mm = 0; mm < 4; mm++) {
            float2 p = unpack2(acc[jl][mm]);
            dst[row + tc + 32 * mm] = p.x + p.y + bv[mm];
        }
    }
}

// ---------------- K2: stats reduce (fp64) + h path + h_out ----------------
__device__ __forceinline__ double blk_red(double v, double* sb) {
    int tid = threadIdx.x;
    sb[tid] = v; __syncthreads();
    for (int o = 128; o > 0; o >>= 1) {
        if (tid < o) sb[tid] += sb[tid + o];
        __syncthreads();
    }
    double r = sb[0]; __syncthreads();
    return r;
}

__global__ void k_finalize(const float* __restrict__ h_in,
                           const float* __restrict__ gamma_h, const float* __restrict__ beta_h,
                           const float* __restrict__ gamma_e, const float* __restrict__ beta_e,
                           float* __restrict__ out_h) {
    __shared__ double sb[256];
    __shared__ float sbroad[2];
    int n = blockIdx.x;
    int tid = threadIdx.x;

    double s = 0.0, q = 0.0;
    for (int p = tid; p < NBLK2; p += 256) {
        s += (double)g_statS[(size_t)n * NBLK2 + p];
        q += (double)g_statQ[(size_t)n * NBLK2 + p];
    }
    s = blk_red(s, sb);
    q = blk_red(q, sb);
    if (tid == 0) {
        double mean = s / (double)ROWS_E;
        double var  = q / (double)ROWS_E - mean * mean;
        float rstd  = (float)(1.0 / sqrt(var + (double)EPS));
        float sc    = gamma_e[n] * rstd;
        g_scaleE[n] = sc;
        g_shiftE[n] = beta_e[n] - (float)mean * sc;
    }

    double hs = 0.0, hq = 0.0;
    for (int r = tid; r < ROWS_H; r += 256) {
        const float* ap = &g_aggp[(size_t)n * NBLK2 + r * 2];
        float agg = ap[0] + ap[1];
        float hn  = g_lin[(size_t)r * HH + n] + agg;  // Uh + agg
        g_hnew[(size_t)r * HH + n] = hn;
        hs += (double)hn; hq += (double)hn * (double)hn;
    }
    hs = blk_red(hs, sb);
    hq = blk_red(hq, sb);
    if (tid == 0) {
        double mean = hs / (double)ROWS_H;
        double var  = hq / (double)ROWS_H - mean * mean;
        float rstd  = (float)(1.0 / sqrt(var + (double)EPS));
        float sc    = gamma_h[n] * rstd;
        sbroad[0]   = sc;
        sbroad[1]   = beta_h[n] - (float)mean * sc;
    }
    __syncthreads();
    float sc = sbroad[0], sh = sbroad[1];
    for (int r = tid; r < ROWS_H; r += 256) {
        float v = fmaf(g_hnew[(size_t)r * HH + n], sc, sh);
        out_h[(size_t)r * HH + n] = h_in[(size_t)r * HH + n] + fmaxf(v, 0.f);
    }
}

// ---------------- K3: e epilogue ----------------
__global__ void k_epi(const float* __restrict__ e_in, float* __restrict__ out_e) {
    int tid = threadIdx.x;
    const float4* en4 = (const float4*)g_enew;
    const float4* ei4 = (const float4*)e_in;
    const float4* sc4 = (const float4*)g_scaleE;
    const float4* sh4 = (const float4*)g_shiftE;
    float4* out4 = (float4*)out_e;
#pragma unroll
    for (int it = 0; it < 4; it++) {
        size_t f = (size_t)blockIdx.x * 1024 + it * 256 + tid;
        int c = (int)(f & 31);
        float4 sc = __ldg(&sc4[c]);
        float4 sh = __ldg(&sh4[c]);
        float4 x  = en4[f];
        float4 ei = ei4[f];
        float4 o;
        o.x = ei.x + fmaxf(fmaf(x.x, sc.x, sh.x), 0.f);
        o.y = ei.y + fmaxf(fmaf(x.y, sc.y, sh.y), 0.f);
        o.z = ei.z + fmaxf(fmaf(x.z, sc.z, sh.z), 0.f);
        o.w = ei.w + fmaxf(fmaf(x.w, sc.w, sh.w), 0.f);
        out4[f] = o;
    }
}

extern "C" void kernel_launch(void* const* d_in, const int* in_sizes, int n_in,
                              void* d_out, int out_size) {
    (void)in_sizes; (void)n_in; (void)out_size;
    const float* h  = (const float*)d_in[0];
    const float* e  = (const float*)d_in[1];
    const float* Uw = (const float*)d_in[3];
    const float* Ub = (const float*)d_in[4];
    const float* Vw = (const float*)d_in[5];
    const float* Vb = (const float*)d_in[6];
    const float* Aw = (const float*)d_in[7];
    const float* Ab = (const float*)d_in[8];
    const float* Bw = (const float*)d_in[9];
    const float* Bb = (const float*)d_in[10];
    const float* Cw = (const float*)d_in[11];
    const float* Cb = (const float*)d_in[12];
    const float* gh = (const float*)d_in[13];
    const float* bh = (const float*)d_in[14];
    const float* ge = (const float*)d_in[15];
    const float* be = (const float*)d_in[16];
    float* out = (float*)d_out;   // [h_out (131072) | e_out (33554432)]

    cudaFuncSetAttribute(k_lin,  cudaFuncAttributeMaxDynamicSharedMemorySize, SMEM_LIN);
    cudaFuncSetAttribute(k_main, cudaFuncAttributeMaxDynamicSharedMemorySize, SM_TOTAL);

    k_lin<<<dim3(ROWS_H / 64, 4), 256, SMEM_LIN>>>(h, Uw, Ub, Vw, Vb, Aw, Ab, Bw, Bb);
    k_main<<<NBLK2, 256, SM_TOTAL>>>(e, Cw, Cb);
    k_finalize<<<HH, 256>>>(h, gh, bh, ge, be, out);
    k_epi<<<ROWS_E * HH / 4096, 256>>>(e, out + ROWS_H * HH);
}

// round 11
// speedup vs baseline: 1.9493x; 1.2393x over previous
#include <cuda_runtime.h>
#include <cuda_bf16.h>
#include <cstdint>

// Problem constants
#define BB 4
#define VV 256
#define HH 128
constexpr int ROWS_H = BB * VV;           // 1024
constexpr int ROWS_E = BB * VV * VV;      // 262144
constexpr int TM     = 128;               // e-rows per block in k_main
constexpr int NBLK2  = ROWS_E / TM;       // 2048
constexpr float EPS  = 1e-5f;

// ---------------- smem geometry for k_main (K chunked: 2 x 64) ----------------
constexpr int LDC    = 72;                  // bf16 elems per tile row (144 B; 9 units, odd)
constexpr int TILE_B = 128 * LDC * 2;       // 18432 B per bf16 tile (128 rows x 64 cols)
constexpr int SM_C2  = 0;                   // 128 floats
constexpr int SM_AHI = 1024;
constexpr int SM_ALO = SM_AHI + TILE_B;     // 19456
constexpr int SM_BHI = SM_ALO + TILE_B;     // 37888  (cp.async dst; BHI+BLO contiguous)
constexpr int SM_BLO = SM_BHI + TILE_B;     // 56320
constexpr int SM_RED = SM_BLO + TILE_B;     // 74752 (3 * 512 floats)
constexpr int SM_TOTAL = SM_RED + 6144;     // 80896

// Scratch
__device__ float g_enew[(size_t)ROWS_E * HH];   // 134 MB
__device__ float g_lin[4 * ROWS_H * HH];        // Uh,Vh,Ah,Bh
__device__ __align__(16) char g_bt[2 * 2 * TILE_B];  // pre-swizzled Cw bf16 [chunk][hi|lo]
__device__ float g_statS[HH * NBLK2];
__device__ float g_statQ[HH * NBLK2];
__device__ float g_aggp[HH * NBLK2];
__device__ float g_hnew[ROWS_H * HH];
__device__ float g_scaleE[HH];
__device__ float g_shiftE[HH];

__device__ __forceinline__ uint32_t smem_u32(const void* p) {
    uint32_t a;
    asm("{ .reg .u64 t; cvta.to.shared.u64 t, %1; cvt.u32.u64 %0, t; }" : "=r"(a) : "l"(p));
    return a;
}
__device__ __forceinline__ void ldmatrix_x4(uint32_t& r0, uint32_t& r1, uint32_t& r2, uint32_t& r3, uint32_t addr) {
    asm volatile("ldmatrix.sync.aligned.m8n8.x4.shared.b16 {%0,%1,%2,%3}, [%4];"
        : "=r"(r0), "=r"(r1), "=r"(r2), "=r"(r3) : "r"(addr) : "memory");
}
__device__ __forceinline__ void mma16816(float (&d)[4], const uint32_t (&a)[4], uint32_t b0, uint32_t b1) {
    asm("mma.sync.aligned.m16n8k16.row.col.f32.bf16.bf16.f32 "
        "{%0,%1,%2,%3}, {%4,%5,%6,%7}, {%8,%9}, {%0,%1,%2,%3};"
        : "+f"(d[0]), "+f"(d[1]), "+f"(d[2]), "+f"(d[3])
        : "r"(a[0]), "r"(a[1]), "r"(a[2]), "r"(a[3]), "r"(b0), "r"(b1));
}
__device__ __forceinline__ void cp_async16(uint32_t smem_dst, const void* gmem_src) {
    asm volatile("cp.async.cg.shared.global [%0], [%1], 16;" :: "r"(smem_dst), "l"(gmem_src) : "memory");
}
__device__ __forceinline__ void cp_async_commit_wait() {
    asm volatile("cp.async.commit_group;" ::: "memory");
    asm volatile("cp.async.wait_group 0;" ::: "memory");
}

__device__ __forceinline__ void cvt_store4(float4 v, char* smem, uint32_t hiOff, uint32_t loOff) {
    __nv_bfloat16 h0 = __float2bfloat16(v.x), h1 = __float2bfloat16(v.y);
    __nv_bfloat16 h2 = __float2bfloat16(v.z), h3 = __float2bfloat16(v.w);
    float r0 = v.x - __bfloat162float(h0), r1 = v.y - __bfloat162float(h1);
    float r2 = v.z - __bfloat162float(h2), r3 = v.w - __bfloat162float(h3);
    __nv_bfloat16 l0 = __float2bfloat16(r0), l1 = __float2bfloat16(r1);
    __nv_bfloat16 l2 = __float2bfloat16(r2), l3 = __float2bfloat16(r3);
    uint2 uh, ul;
    uh.x = ((uint32_t)__bfloat16_as_ushort(h1) << 16) | __bfloat16_as_ushort(h0);
    uh.y = ((uint32_t)__bfloat16_as_ushort(h3) << 16) | __bfloat16_as_ushort(h2);
    ul.x = ((uint32_t)__bfloat16_as_ushort(l1) << 16) | __bfloat16_as_ushort(l0);
    ul.y = ((uint32_t)__bfloat16_as_ushort(l3) << 16) | __bfloat16_as_ushort(l2);
    *(uint2*)(smem + hiOff) = uh;
    *(uint2*)(smem + loOff) = ul;
}

// ---------------- K1: HMMA Ce GEMM + e_new + gates + agg + stats ----------------
__global__ void __launch_bounds__(256, 2)
k_main(const float* __restrict__ e, const float* __restrict__ Cb) {
    extern __shared__ char sm[];
    uint32_t smb = smem_u32(sm);
    int tid = threadIdx.x;
    int wid = tid >> 5, lane = tid & 31;

    int blk = blockIdx.x;
    int rbase = blk * TM;
    int bi = blk >> 1;            // b*V + i
    int b  = bi >> 8;
    int j0 = (blk & 1) * TM;      // j range start

    // c2 = Cb + Bh[bi]
    if (tid < HH)
        ((float*)(sm + SM_C2))[tid] = Cb[tid] + g_lin[(size_t)3 * ROWS_H * HH + (size_t)bi * HH + tid];

    int wm = wid >> 1, wn = wid & 1;
    float d[2][8][4];
#pragma unroll
    for (int mt = 0; mt < 2; mt++)
#pragma unroll
        for (int nt = 0; nt < 8; nt++)
#pragma unroll
            for (int q = 0; q < 4; q++) d[mt][nt][q] = 0.f;

    uint32_t aLaneOff = (uint32_t)(wm * 32 + (lane & 15)) * (LDC * 2) + (lane >> 4) * 16;
    uint32_t bLaneOff = (uint32_t)(wn * 64 + (((lane >> 4) & 1) * 8) + (lane & 7)) * (LDC * 2)
                      + ((lane >> 3) & 1) * 16;

#pragma unroll
    for (int ch = 0; ch < 2; ch++) {
        // B tiles (hi|lo contiguous): cp.async from pre-converted gmem
        {
            const char* bsrc = g_bt + (size_t)ch * 2 * TILE_B;
            for (int i = tid; i < 2 * TILE_B / 16; i += 256)
                cp_async16(smb + SM_BHI + i * 16, bsrc + i * 16);
        }
        // A: load e chunk, convert to bf16 hi/lo in smem
        const float* eb = e + (size_t)rbase * HH + ch * 64;
        for (int idx = tid; idx < 128 * 16; idx += 256) {
            int row = idx >> 4, c4 = idx & 15;
            uint32_t off = (uint32_t)row * (LDC * 2) + c4 * 8;
            float4 ev = *(const float4*)&eb[(size_t)row * HH + c4 * 4];
            cvt_store4(ev, sm, SM_AHI + off, SM_ALO + off);
        }
        cp_async_commit_wait();
        __syncthreads();

#pragma unroll
        for (int p = 0; p < 3; p++) {
            uint32_t aBase = smb + ((p == 2) ? SM_ALO : SM_AHI) + aLaneOff;
            uint32_t bBase = smb + ((p == 1) ? SM_BLO : SM_BHI) + bLaneOff;
#pragma unroll
            for (int kk = 0; kk < 4; kk++) {
                uint32_t a0[4], a1[4];
                ldmatrix_x4(a0[0], a0[1], a0[2], a0[3], aBase + kk * 32);
                ldmatrix_x4(a1[0], a1[1], a1[2], a1[3], aBase + kk * 32 + 16 * (LDC * 2));
                uint32_t bb[16];
#pragma unroll
                for (int q = 0; q < 4; q++)
                    ldmatrix_x4(bb[q * 4], bb[q * 4 + 1], bb[q * 4 + 2], bb[q * 4 + 3],
                                bBase + kk * 32 + (uint32_t)q * 16 * (LDC * 2));
#pragma unroll
                for (int nt = 0; nt < 8; nt++) {
                    uint32_t b0 = bb[(nt >> 1) * 4 + (nt & 1) * 2];
                    uint32_t b1 = bb[(nt >> 1) * 4 + (nt & 1) * 2 + 1];
                    mma16816(d[0][nt], a0, b0, b1);
                    mma16816(d[1][nt], a1, b0, b1);
                }
            }
        }
        __syncthreads();   // tiles consumed; next chunk may overwrite
    }

    // -------- fragment-direct epilogue (no Ds staging) --------
    // value (mt,nt,q): row = wm*32 + mt*16 + (q>=2)*8 + (lane>>2), col = wn*64 + nt*8 + (lane&3)*2 + (q&1)
    {
        int g = lane >> 2, t2 = (lane & 3) * 2;
        const float* c2s = (const float*)(sm + SM_C2);
        const float* ahB = g_lin + (size_t)2 * ROWS_H * HH + (size_t)(b * VV + j0) * HH;
        const float* vhB = g_lin + (size_t)1 * ROWS_H * HH + (size_t)(b * VV + j0) * HH;
        float* enB = g_enew + (size_t)rbase * HH;
        float* redS = (float*)(sm + SM_RED);
        float* redQ = redS + 512;
        float* redA = redQ + 512;

#pragma unroll
        for (int nt = 0; nt < 8; nt++) {
            int c = wn * 64 + nt * 8 + t2;
            float c2a = c2s[c], c2b = c2s[c + 1];
            float pS0 = 0.f, pS1 = 0.f, pQ0 = 0.f, pQ1 = 0.f, pA0 = 0.f, pA1 = 0.f;
#pragma unroll
            for (int mt = 0; mt < 2; mt++) {
#pragma unroll
                for (int h = 0; h < 2; h++) {
                    int r = wm * 32 + mt * 16 + h * 8 + g;
                    float2 ahv = *(const float2*)&ahB[(size_t)r * HH + c];
                    float2 vhv = *(const float2*)&vhB[(size_t)r * HH + c];
                    float x0 = d[mt][nt][h * 2 + 0] + c2a + ahv.x;
                    float x1 = d[mt][nt][h * 2 + 1] + c2b + ahv.y;
                    *(float2*)&enB[(size_t)r * HH + c] = make_float2(x0, x1);
                    pS0 += x0; pS1 += x1;
                    pQ0 = fmaf(x0, x0, pQ0); pQ1 = fmaf(x1, x1, pQ1);
                    pA0 = fmaf(vhv.x, 1.f / (1.f + __expf(-x0)), pA0);
                    pA1 = fmaf(vhv.y, 1.f / (1.f + __expf(-x1)), pA1);
                }
            }
            // reduce over the 8 row-groups (lanes ^4, ^8, ^16 share columns)
#pragma unroll
            for (int m = 4; m <= 16; m <<= 1) {
                pS0 += __shfl_xor_sync(0xffffffffu, pS0, m);
                pS1 += __shfl_xor_sync(0xffffffffu, pS1, m);
                pQ0 += __shfl_xor_sync(0xffffffffu, pQ0, m);
                pQ1 += __shfl_xor_sync(0xffffffffu, pQ1, m);
                pA0 += __shfl_xor_sync(0xffffffffu, pA0, m);
                pA1 += __shfl_xor_sync(0xffffffffu, pA1, m);
            }
            if (g == 0) {
                redS[wm * 128 + c] = pS0; redS[wm * 128 + c + 1] = pS1;
                redQ[wm * 128 + c] = pQ0; redQ[wm * 128 + c + 1] = pQ1;
                redA[wm * 128 + c] = pA0; redA[wm * 128 + c + 1] = pA1;
            }
        }
    }
    __syncthreads();
    if (tid < HH) {
        float* redS = (float*)(sm + SM_RED);
        float* redQ = redS + 512;
        float* redA = redQ + 512;
        float S = 0.f, Q = 0.f, A = 0.f;
#pragma unroll
        for (int w = 0; w < 4; w++) {
            S += redS[w * 128 + tid];
            Q += redQ[w * 128 + tid];
            A += redA[w * 128 + tid];
        }
        g_statS[(size_t)tid * NBLK2 + blk] = S;
        g_statQ[(size_t)tid * NBLK2 + blk] = Q;
        g_aggp[(size_t)tid * NBLK2 + blk]  = A;
    }
}

// ---------------- K0: four small linears + Cw pre-convert (y==4) ----------------
constexpr int WS_STRIDE = 132;
constexpr int SMEM_LIN = (HH * WS_STRIDE + 64 * HH) * 4;

__device__ __forceinline__ void fma2(unsigned long long& d, unsigned long long a, unsigned long long b) {
    asm("fma.rn.f32x2 %0, %1, %2, %0;" : "+l"(d) : "l"(a), "l"(b));
}
__device__ __forceinline__ float2 unpack2(unsigned long long v) {
    float2 r; asm("mov.b64 {%0,%1}, %2;" : "=f"(r.x), "=f"(r.y) : "l"(v)); return r;
}

__global__ void k_lin(const float* __restrict__ h,
                      const float* __restrict__ W0, const float* __restrict__ b0,
                      const float* __restrict__ W1, const float* __restrict__ b1,
                      const float* __restrict__ W2, const float* __restrict__ b2,
                      const float* __restrict__ W3, const float* __restrict__ b3,
                      const float* __restrict__ Cw) {
    if (blockIdx.y == 4) {
        // pre-convert Cw chunk (blockIdx.x&1) into g_bt, same layout as smem B tiles
        int ch = blockIdx.x & 1;
        if (blockIdx.x >= 2) return;
        char* dst = g_bt + (size_t)ch * 2 * TILE_B;
        const float* wb = Cw + ch * 64;
        for (int idx = threadIdx.x; idx < 128 * 16; idx += 256) {
            int row = idx >> 4, c4 = idx & 15;
            uint32_t off = (uint32_t)row * (LDC * 2) + c4 * 8;
            float4 wv = *(const float4*)&wb[(size_t)row * HH + c4 * 4];
            cvt_store4(wv, dst, off, TILE_B + off);
        }
        return;
    }
    extern __shared__ float smf[];
    float* Ws = smf;
    float* As = Ws + HH * WS_STRIDE;

    int m = blockIdx.y;
    const float* W    = (m == 0) ? W0 : (m == 1) ? W1 : (m == 2) ? W2 : W3;
    const float* bias = (m == 0) ? b0 : (m == 1) ? b1 : (m == 2) ? b2 : b3;

    int tid = threadIdx.x;
    for (int i = tid; i < HH * 32; i += 256) {
        int n = i >> 5, kc = i & 31;
        *(float4*)&Ws[n * WS_STRIDE + kc * 4] = *(const float4*)&W[n * HH + kc * 4];
    }
    int r0 = blockIdx.x * 64;
    const float4* hsrc = (const float4*)(h + (size_t)r0 * HH);
    for (int i = tid; i < 64 * 32; i += 256) ((float4*)As)[i] = hsrc[i];
    __syncthreads();

    int tr = tid >> 5, tc = tid & 31;
    int jj0 = tr * 8;
    unsigned long long acc[8][4];
#pragma unroll
    for (int jl = 0; jl < 8; jl++)
#pragma unroll
        for (int mm = 0; mm < 4; mm++) acc[jl][mm] = 0ull;
#pragma unroll 4
    for (int k = 0; k < HH; k += 4) {
        ulonglong2 w0 = *(const ulonglong2*)&Ws[(tc +  0) * WS_STRIDE + k];
        ulonglong2 w1 = *(const ulonglong2*)&Ws[(tc + 32) * WS_STRIDE + k];
        ulonglong2 w2 = *(const ulonglong2*)&Ws[(tc + 64) * WS_STRIDE + k];
        ulonglong2 w3 = *(const ulonglong2*)&Ws[(tc + 96) * WS_STRIDE + k];
#pragma unroll
        for (int jl = 0; jl < 8; jl++) {
            ulonglong2 a = *(const ulonglong2*)&As[(jj0 + jl) * HH + k];
            fma2(acc[jl][0], a.x, w0.x); fma2(acc[jl][0], a.y, w0.y);
            fma2(acc[jl][1], a.x, w1.x); fma2(acc[jl][1], a.y, w1.y);
            fma2(acc[jl][2], a.x, w2.x); fma2(acc[jl][2], a.y, w2.y);
            fma2(acc[jl][3], a.x, w3.x); fma2(acc[jl][3], a.y, w3.y);
        }
    }
    float bv[4];
#pragma unroll
    for (int mm = 0; mm < 4; mm++) bv[mm] = bias[tc + 32 * mm];
    float* dst = g_lin + (size_t)m * ROWS_H * HH;
#pragma unroll
    for (int jl = 0; jl < 8; jl++) {
        size_t row = (size_t)(r0 + jj0 + jl) * HH;
#pragma unroll
        for (int mm = 0; mm < 4; mm++) {
            float2 p = unpack2(acc[jl][mm]);
            dst[row + tc + 32 * mm] = p.x + p.y + bv[mm];
        }
    }
}

// ---------------- K2: stats reduce (fp64) + h path + h_out ----------------
__device__ __forceinline__ double blk_red(double v, double* sb) {
    int tid = threadIdx.x;
    sb[tid] = v; __syncthreads();
    for (int o = 128; o > 0; o >>= 1) {
        if (tid < o) sb[tid] += sb[tid + o];
        __syncthreads();
    }
    double r = sb[0]; __syncthreads();
    return r;
}

__global__ void k_finalize(const float* __restrict__ h_in,
                           const float* __restrict__ gamma_h, const float* __restrict__ beta_h,
                           const float* __restrict__ gamma_e, const float* __restrict__ beta_e,
                           float* __restrict__ out_h) {
    __shared__ double sb[256];
    __shared__ float sbroad[2];
    int n = blockIdx.x;
    int tid = threadIdx.x;

    double s = 0.0, q = 0.0;
    for (int p = tid; p < NBLK2; p += 256) {
        s += (double)g_statS[(size_t)n * NBLK2 + p];
        q += (double)g_statQ[(size_t)n * NBLK2 + p];
    }
    s = blk_red(s, sb);
    q = blk_red(q, sb);
    if (tid == 0) {
        double mean = s / (double)ROWS_E;
        double var  = q / (double)ROWS_E - mean * mean;
        float rstd  = (float)(1.0 / sqrt(var + (double)EPS));
        float sc    = gamma_e[n] * rstd;
        g_scaleE[n] = sc;
        g_shiftE[n] = beta_e[n] - (float)mean * sc;
    }

    double hs = 0.0, hq = 0.0;
    for (int r = tid; r < ROWS_H; r += 256) {
        const float* ap = &g_aggp[(size_t)n * NBLK2 + r * 2];
        float agg = ap[0] + ap[1];
        float hn  = g_lin[(size_t)r * HH + n] + agg;  // Uh + agg
        g_hnew[(size_t)r * HH + n] = hn;
        hs += (double)hn; hq += (double)hn * (double)hn;
    }
    hs = blk_red(hs, sb);
    hq = blk_red(hq, sb);
    if (tid == 0) {
        double mean = hs / (double)ROWS_H;
        double var  = hq / (double)ROWS_H - mean * mean;
        float rstd  = (float)(1.0 / sqrt(var + (double)EPS));
        float sc    = gamma_h[n] * rstd;
        sbroad[0]   = sc;
        sbroad[1]   = beta_h[n] - (float)mean * sc;
    }
    __syncthreads();
    float sc = sbroad[0], sh = sbroad[1];
    for (int r = tid; r < ROWS_H; r += 256) {
        float v = fmaf(g_hnew[(size_t)r * HH + n], sc, sh);
        out_h[(size_t)r * HH + n] = h_in[(size_t)r * HH + n] + fmaxf(v, 0.f);
    }
}

// ---------------- K3: e epilogue ----------------
__global__ void k_epi(const float* __restrict__ e_in, float* __restrict__ out_e) {
    int tid = threadIdx.x;
    const float4* en4 = (const float4*)g_enew;
    const float4* ei4 = (const float4*)e_in;
    const float4* sc4 = (const float4*)g_scaleE;
    const float4* sh4 = (const float4*)g_shiftE;
    float4* out4 = (float4*)out_e;
#pragma unroll
    for (int it = 0; it < 4; it++) {
        size_t f = (size_t)blockIdx.x * 1024 + it * 256 + tid;
        int c = (int)(f & 31);
        float4 sc = __ldg(&sc4[c]);
        float4 sh = __ldg(&sh4[c]);
        float4 x  = en4[f];
        float4 ei = ei4[f];
        float4 o;
        o.x = ei.x + fmaxf(fmaf(x.x, sc.x, sh.x), 0.f);
        o.y = ei.y + fmaxf(fmaf(x.y, sc.y, sh.y), 0.f);
        o.z = ei.z + fmaxf(fmaf(x.z, sc.z, sh.z), 0.f);
        o.w = ei.w + fmaxf(fmaf(x.w, sc.w, sh.w), 0.f);
        out4[f] = o;
    }
}

extern "C" void kernel_launch(void* const* d_in, const int* in_sizes, int n_in,
                              void* d_out, int out_size) {
    (void)in_sizes; (void)n_in; (void)out_size;
    const float* h  = (const float*)d_in[0];
    const float* e  = (const float*)d_in[1];
    const float* Uw = (const float*)d_in[3];
    const float* Ub = (const float*)d_in[4];
    const float* Vw = (const float*)d_in[5];
    const float* Vb = (const float*)d_in[6];
    const float* Aw = (const float*)d_in[7];
    const float* Ab = (const float*)d_in[8];
    const float* Bw = (const float*)d_in[9];
    const float* Bb = (const float*)d_in[10];
    const float* Cw = (const float*)d_in[11];
    const float* Cb = (const float*)d_in[12];
    const float* gh = (const float*)d_in[13];
    const float* bh = (const float*)d_in[14];
    const float* ge = (const float*)d_in[15];
    const float* be = (const float*)d_in[16];
    float* out = (float*)d_out;   // [h_out (131072) | e_out (33554432)]

    cudaFuncSetAttribute(k_lin,  cudaFuncAttributeMaxDynamicSharedMemorySize, SMEM_LIN);
    cudaFuncSetAttribute(k_main, cudaFuncAttributeMaxDynamicSharedMemorySize, SM_TOTAL);

    k_lin<<<dim3(ROWS_H / 64, 5), 256, SMEM_LIN>>>(h, Uw, Ub, Vw, Vb, Aw, Ab, Bw, Bb, Cw);
    k_main<<<NBLK2, 256, SM_TOTAL>>>(e, Cb);
    k_finalize<<<HH, 256>>>(h, gh, bh, ge, be, out);
    k_epi<<<ROWS_E * HH / 4096, 256>>>(e, out + ROWS_H * HH);
}

// round 12
// speedup vs baseline: 2.2387x; 1.1485x over previous
#include <cuda_runtime.h>
#include <cuda_fp16.h>
#include <cstdint>

// Problem constants
#define BB 4
#define VV 256
#define HH 128
constexpr int ROWS_H = BB * VV;           // 1024
constexpr int ROWS_E = BB * VV * VV;      // 262144
constexpr int TM     = 128;               // e-rows per block in k_main
constexpr int NBLK2  = ROWS_E / TM;       // 2048
constexpr float EPS  = 1e-5f;

// ---------------- smem geometry for k_main (K chunked: 2 x 64, fp16 2-pass) ----------------
constexpr int LDC    = 72;                  // fp16 elems per tile row (144 B; 9 units, odd)
constexpr int TILE_B = 128 * LDC * 2;       // 18432 B per fp16 tile (128 rows x 64 cols)
constexpr int SM_C2  = 0;                   // 128 floats
constexpr int SM_AHI = 1024;
constexpr int SM_ALO = SM_AHI + TILE_B;     // 19456
constexpr int SM_BW  = SM_ALO + TILE_B;     // 37888  (single weight tile; cp.async dst)
constexpr int SM_RED = SM_BW + TILE_B;      // 56320 (3 * 512 floats)
constexpr int SM_TOTAL = SM_RED + 6144;     // 62464 B

// Scratch
__device__ float g_enew[(size_t)ROWS_E * HH];   // 134 MB
__device__ float g_lin[4 * ROWS_H * HH];        // Uh,Vh,Ah,Bh
__device__ __align__(16) char g_bt[2 * TILE_B]; // pre-swizzled Cw fp16 [chunk]
__device__ float g_statS[HH * NBLK2];
__device__ float g_statQ[HH * NBLK2];
__device__ float g_aggp[HH * NBLK2];
__device__ float g_hnew[ROWS_H * HH];
__device__ float g_scaleE[HH];
__device__ float g_shiftE[HH];

__device__ __forceinline__ uint32_t smem_u32(const void* p) {
    uint32_t a;
    asm("{ .reg .u64 t; cvta.to.shared.u64 t, %1; cvt.u32.u64 %0, t; }" : "=r"(a) : "l"(p));
    return a;
}
__device__ __forceinline__ void ldmatrix_x4(uint32_t& r0, uint32_t& r1, uint32_t& r2, uint32_t& r3, uint32_t addr) {
    asm volatile("ldmatrix.sync.aligned.m8n8.x4.shared.b16 {%0,%1,%2,%3}, [%4];"
        : "=r"(r0), "=r"(r1), "=r"(r2), "=r"(r3) : "r"(addr) : "memory");
}
__device__ __forceinline__ void mma16816(float (&d)[4], const uint32_t (&a)[4], uint32_t b0, uint32_t b1) {
    asm("mma.sync.aligned.m16n8k16.row.col.f32.f16.f16.f32 "
        "{%0,%1,%2,%3}, {%4,%5,%6,%7}, {%8,%9}, {%0,%1,%2,%3};"
        : "+f"(d[0]), "+f"(d[1]), "+f"(d[2]), "+f"(d[3])
        : "r"(a[0]), "r"(a[1]), "r"(a[2]), "r"(a[3]), "r"(b0), "r"(b1));
}
__device__ __forceinline__ void cp_async16(uint32_t smem_dst, const void* gmem_src) {
    asm volatile("cp.async.cg.shared.global [%0], [%1], 16;" :: "r"(smem_dst), "l"(gmem_src) : "memory");
}
__device__ __forceinline__ void cp_async_commit_wait() {
    asm volatile("cp.async.commit_group;" ::: "memory");
    asm volatile("cp.async.wait_group 0;" ::: "memory");
}

// A conversion: hi = fp16(v), lo = fp16(v - hi); two tiles
__device__ __forceinline__ void cvtA_store4(float4 v, char* smem, uint32_t hiOff, uint32_t loOff) {
    __half h0 = __float2half_rn(v.x), h1 = __float2half_rn(v.y);
    __half h2 = __float2half_rn(v.z), h3 = __float2half_rn(v.w);
    __half l0 = __float2half_rn(v.x - __half2float(h0));
    __half l1 = __float2half_rn(v.y - __half2float(h1));
    __half l2 = __float2half_rn(v.z - __half2float(h2));
    __half l3 = __float2half_rn(v.w - __half2float(h3));
    uint2 uh, ul;
    uh.x = ((uint32_t)__half_as_ushort(h1) << 16) | __half_as_ushort(h0);
    uh.y = ((uint32_t)__half_as_ushort(h3) << 16) | __half_as_ushort(h2);
    ul.x = ((uint32_t)__half_as_ushort(l1) << 16) | __half_as_ushort(l0);
    ul.y = ((uint32_t)__half_as_ushort(l3) << 16) | __half_as_ushort(l2);
    *(uint2*)(smem + hiOff) = uh;
    *(uint2*)(smem + loOff) = ul;
}
// B conversion: single fp16 tile
__device__ __forceinline__ void cvtB_store4(float4 v, char* smem, uint32_t off) {
    __half h0 = __float2half_rn(v.x), h1 = __float2half_rn(v.y);
    __half h2 = __float2half_rn(v.z), h3 = __float2half_rn(v.w);
    uint2 u;
    u.x = ((uint32_t)__half_as_ushort(h1) << 16) | __half_as_ushort(h0);
    u.y = ((uint32_t)__half_as_ushort(h3) << 16) | __half_as_ushort(h2);
    *(uint2*)(smem + off) = u;
}

// ---------------- K1: HMMA Ce GEMM (fp16 2-pass) + e_new + gates + agg + stats ----------------
__global__ void __launch_bounds__(256, 2)
k_main(const float* __restrict__ e, const float* __restrict__ Cb) {
    extern __shared__ char sm[];
    uint32_t smb = smem_u32(sm);
    int tid = threadIdx.x;
    int wid = tid >> 5, lane = tid & 31;

    int blk = blockIdx.x;
    int rbase = blk * TM;
    int bi = blk >> 1;            // b*V + i
    int b  = bi >> 8;
    int j0 = (blk & 1) * TM;      // j range start

    // c2 = Cb + Bh[bi]
    if (tid < HH)
        ((float*)(sm + SM_C2))[tid] = Cb[tid] + g_lin[(size_t)3 * ROWS_H * HH + (size_t)bi * HH + tid];

    int wm = wid >> 1, wn = wid & 1;
    float d[2][8][4];
#pragma unroll
    for (int mt = 0; mt < 2; mt++)
#pragma unroll
        for (int nt = 0; nt < 8; nt++)
#pragma unroll
            for (int q = 0; q < 4; q++) d[mt][nt][q] = 0.f;

    uint32_t aLaneOff = (uint32_t)(wm * 32 + (lane & 15)) * (LDC * 2) + (lane >> 4) * 16;
    uint32_t bLaneOff = (uint32_t)(wn * 64 + (((lane >> 4) & 1) * 8) + (lane & 7)) * (LDC * 2)
                      + ((lane >> 3) & 1) * 16;

#pragma unroll
    for (int ch = 0; ch < 2; ch++) {
        // B tile: cp.async from pre-converted gmem
        {
            const char* bsrc = g_bt + (size_t)ch * TILE_B;
            for (int i = tid; i < TILE_B / 16; i += 256)
                cp_async16(smb + SM_BW + i * 16, bsrc + i * 16);
        }
        // A: load e chunk, convert to fp16 hi/lo in smem
        const float* eb = e + (size_t)rbase * HH + ch * 64;
        for (int idx = tid; idx < 128 * 16; idx += 256) {
            int row = idx >> 4, c4 = idx & 15;
            uint32_t off = (uint32_t)row * (LDC * 2) + c4 * 8;
            float4 ev = *(const float4*)&eb[(size_t)row * HH + c4 * 4];
            cvtA_store4(ev, sm, SM_AHI + off, SM_ALO + off);
        }
        cp_async_commit_wait();
        __syncthreads();

        uint32_t aHiBase = smb + SM_AHI + aLaneOff;
        uint32_t aLoBase = smb + SM_ALO + aLaneOff;
        uint32_t bBase   = smb + SM_BW  + bLaneOff;
#pragma unroll
        for (int kk = 0; kk < 4; kk++) {
            // B fragments once (shared by hi and lo passes)
            uint32_t bb[16];
#pragma unroll
            for (int q = 0; q < 4; q++)
                ldmatrix_x4(bb[q * 4], bb[q * 4 + 1], bb[q * 4 + 2], bb[q * 4 + 3],
                            bBase + kk * 32 + (uint32_t)q * 16 * (LDC * 2));
            uint32_t a0[4], a1[4], c0[4], c1[4];
            ldmatrix_x4(a0[0], a0[1], a0[2], a0[3], aHiBase + kk * 32);
            ldmatrix_x4(a1[0], a1[1], a1[2], a1[3], aHiBase + kk * 32 + 16 * (LDC * 2));
            ldmatrix_x4(c0[0], c0[1], c0[2], c0[3], aLoBase + kk * 32);
            ldmatrix_x4(c1[0], c1[1], c1[2], c1[3], aLoBase + kk * 32 + 16 * (LDC * 2));
#pragma unroll
            for (int nt = 0; nt < 8; nt++) {
                uint32_t b0 = bb[(nt >> 1) * 4 + (nt & 1) * 2];
                uint32_t b1 = bb[(nt >> 1) * 4 + (nt & 1) * 2 + 1];
                mma16816(d[0][nt], a0, b0, b1);
                mma16816(d[1][nt], a1, b0, b1);
                mma16816(d[0][nt], c0, b0, b1);
                mma16816(d[1][nt], c1, b0, b1);
            }
        }
        __syncthreads();   // tiles consumed; next chunk may overwrite
    }

    // -------- fragment-direct epilogue --------
    {
        int g = lane >> 2, t2 = (lane & 3) * 2;
        const float* c2s = (const float*)(sm + SM_C2);
        const float* ahB = g_lin + (size_t)2 * ROWS_H * HH + (size_t)(b * VV + j0) * HH;
        const float* vhB = g_lin + (size_t)1 * ROWS_H * HH + (size_t)(b * VV + j0) * HH;
        float* enB = g_enew + (size_t)rbase * HH;
        float* redS = (float*)(sm + SM_RED);
        float* redQ = redS + 512;
        float* redA = redQ + 512;

#pragma unroll
        for (int nt = 0; nt < 8; nt++) {
            int c = wn * 64 + nt * 8 + t2;
            float c2a = c2s[c], c2b = c2s[c + 1];
            float pS0 = 0.f, pS1 = 0.f, pQ0 = 0.f, pQ1 = 0.f, pA0 = 0.f, pA1 = 0.f;
#pragma unroll
            for (int mt = 0; mt < 2; mt++) {
#pragma unroll
                for (int h = 0; h < 2; h++) {
                    int r = wm * 32 + mt * 16 + h * 8 + g;
                    float2 ahv = *(const float2*)&ahB[(size_t)r * HH + c];
                    float2 vhv = *(const float2*)&vhB[(size_t)r * HH + c];
                    float x0 = d[mt][nt][h * 2 + 0] + c2a + ahv.x;
                    float x1 = d[mt][nt][h * 2 + 1] + c2b + ahv.y;
                    *(float2*)&enB[(size_t)r * HH + c] = make_float2(x0, x1);
                    pS0 += x0; pS1 += x1;
                    pQ0 = fmaf(x0, x0, pQ0); pQ1 = fmaf(x1, x1, pQ1);
                    pA0 = fmaf(vhv.x, 1.f / (1.f + __expf(-x0)), pA0);
                    pA1 = fmaf(vhv.y, 1.f / (1.f + __expf(-x1)), pA1);
                }
            }
#pragma unroll
            for (int m = 4; m <= 16; m <<= 1) {
                pS0 += __shfl_xor_sync(0xffffffffu, pS0, m);
                pS1 += __shfl_xor_sync(0xffffffffu, pS1, m);
                pQ0 += __shfl_xor_sync(0xffffffffu, pQ0, m);
                pQ1 += __shfl_xor_sync(0xffffffffu, pQ1, m);
                pA0 += __shfl_xor_sync(0xffffffffu, pA0, m);
                pA1 += __shfl_xor_sync(0xffffffffu, pA1, m);
            }
            if (g == 0) {
                redS[wm * 128 + c] = pS0; redS[wm * 128 + c + 1] = pS1;
                redQ[wm * 128 + c] = pQ0; redQ[wm * 128 + c + 1] = pQ1;
                redA[wm * 128 + c] = pA0; redA[wm * 128 + c + 1] = pA1;
            }
        }
    }
    __syncthreads();
    if (tid < HH) {
        float* redS = (float*)(sm + SM_RED);
        float* redQ = redS + 512;
        float* redA = redQ + 512;
        float S = 0.f, Q = 0.f, A = 0.f;
#pragma unroll
        for (int w = 0; w < 4; w++) {
            S += redS[w * 128 + tid];
            Q += redQ[w * 128 + tid];
            A += redA[w * 128 + tid];
        }
        g_statS[(size_t)tid * NBLK2 + blk] = S;
        g_statQ[(size_t)tid * NBLK2 + blk] = Q;
        g_aggp[(size_t)tid * NBLK2 + blk]  = A;
    }
}

// ---------------- K0: four small linears + Cw pre-convert (y==4) ----------------
constexpr int WS_STRIDE = 132;
constexpr int SMEM_LIN = (HH * WS_STRIDE + 64 * HH) * 4;

__device__ __forceinline__ void fma2(unsigned long long& d, unsigned long long a, unsigned long long b) {
    asm("fma.rn.f32x2 %0, %1, %2, %0;" : "+l"(d) : "l"(a), "l"(b));
}
__device__ __forceinline__ float2 unpack2(unsigned long long v) {
    float2 r; asm("mov.b64 {%0,%1}, %2;" : "=f"(r.x), "=f"(r.y) : "l"(v)); return r;
}

__global__ void k_lin(const float* __restrict__ h,
                      const float* __restrict__ W0, const float* __restrict__ b0,
                      const float* __restrict__ W1, const float* __restrict__ b1,
                      const float* __restrict__ W2, const float* __restrict__ b2,
                      const float* __restrict__ W3, const float* __restrict__ b3,
                      const float* __restrict__ Cw) {
    if (blockIdx.y == 4) {
        int ch = blockIdx.x & 1;
        if (blockIdx.x >= 2) return;
        char* dst = g_bt + (size_t)ch * TILE_B;
        const float* wb = Cw + ch * 64;
        for (int idx = threadIdx.x; idx < 128 * 16; idx += 256) {
            int row = idx >> 4, c4 = idx & 15;
            uint32_t off = (uint32_t)row * (LDC * 2) + c4 * 8;
            float4 wv = *(const float4*)&wb[(size_t)row * HH + c4 * 4];
            cvtB_store4(wv, dst, off);
        }
        return;
    }
    extern __shared__ float smf[];
    float* Ws = smf;
    float* As = Ws + HH * WS_STRIDE;

    int m = blockIdx.y;
    const float* W    = (m == 0) ? W0 : (m == 1) ? W1 : (m == 2) ? W2 : W3;
    const float* bias = (m == 0) ? b0 : (m == 1) ? b1 : (m == 2) ? b2 : b3;

    int tid = threadIdx.x;
    for (int i = tid; i < HH * 32; i += 256) {
        int n = i >> 5, kc = i & 31;
        *(float4*)&Ws[n * WS_STRIDE + kc * 4] = *(const float4*)&W[n * HH + kc * 4];
    }
    int r0 = blockIdx.x * 64;
    const float4* hsrc = (const float4*)(h + (size_t)r0 * HH);
    for (int i = tid; i < 64 * 32; i += 256) ((float4*)As)[i] = hsrc[i];
    __syncthreads();

    int tr = tid >> 5, tc = tid & 31;
    int jj0 = tr * 8;
    unsigned long long acc[8][4];
#pragma unroll
    for (int jl = 0; jl < 8; jl++)
#pragma unroll
        for (int mm = 0; mm < 4; mm++) acc[jl][mm] = 0ull;
#pragma unroll 4
    for (int k = 0; k < HH; k += 4) {
        ulonglong2 w0 = *(const ulonglong2*)&Ws[(tc +  0) * WS_STRIDE + k];
        ulonglong2 w1 = *(const ulonglong2*)&Ws[(tc + 32) * WS_STRIDE + k];
        ulonglong2 w2 = *(const ulonglong2*)&Ws[(tc + 64) * WS_STRIDE + k];
        ulonglong2 w3 = *(const ulonglong2*)&Ws[(tc + 96) * WS_STRIDE + k];
#pragma unroll
        for (int jl = 0; jl < 8; jl++) {
            ulonglong2 a = *(const ulonglong2*)&As[(jj0 + jl) * HH + k];
            fma2(acc[jl][0], a.x, w0.x); fma2(acc[jl][0], a.y, w0.y);
            fma2(acc[jl][1], a.x, w1.x); fma2(acc[jl][1], a.y, w1.y);
            fma2(acc[jl][2], a.x, w2.x); fma2(acc[jl][2], a.y, w2.y);
            fma2(acc[jl][3], a.x, w3.x); fma2(acc[jl][3], a.y, w3.y);
        }
    }
    float bv[4];
#pragma unroll
    for (int mm = 0; mm < 4; mm++) bv[mm] = bias[tc + 32 * mm];
    float* dst = g_lin + (size_t)m * ROWS_H * HH;
#pragma unroll
    for (int jl = 0; jl < 8; jl++) {
        size_t row = (size_t)(r0 + jj0 + jl) * HH;
#pragma unroll
        for (int mm = 0; mm < 4; mm++) {
            float2 p = unpack2(acc[jl][mm]);
            dst[row + tc + 32 * mm] = p.x + p.y + bv[mm];
        }
    }
}

// ---------------- K2: stats reduce (fp64) + h path + h_out ----------------
__device__ __forceinline__ double blk_red(double v, double* sb) {
    int tid = threadIdx.x;
    sb[tid] = v; __syncthreads();
    for (int o = 128; o > 0; o >>= 1) {
        if (tid < o) sb[tid] += sb[tid + o];
        __syncthreads();
    }
    double r = sb[0]; __syncthreads();
    return r;
}

__global__ void k_finalize(const float* __restrict__ h_in,
                           const float* __restrict__ gamma_h, const float* __restrict__ beta_h,
                           const float* __restrict__ gamma_e, const float* __restrict__ beta_e,
                           float* __restrict__ out_h) {
    __shared__ double sb[256];
    __shared__ float sbroad[2];
    int n = blockIdx.x;
    int tid = threadIdx.x;

    double s = 0.0, q = 0.0;
    for (int p = tid; p < NBLK2; p += 256) {
        s += (double)g_statS[(size_t)n * NBLK2 + p];
        q += (double)g_statQ[(size_t)n * NBLK2 + p];
    }
    s = blk_red(s, sb);
    q = blk_red(q, sb);
    if (tid == 0) {
        double mean = s / (double)ROWS_E;
        double var  = q / (double)ROWS_E - mean * mean;
        float rstd  = (float)(1.0 / sqrt(var + (double)EPS));
        float sc    = gamma_e[n] * rstd;
        g_scaleE[n] = sc;
        g_shiftE[n] = beta_e[n] - (float)mean * sc;
    }

    double hs = 0.0, hq = 0.0;
    for (int r = tid; r < ROWS_H; r += 256) {
        const float* ap = &g_aggp[(size_t)n * NBLK2 + r * 2];
        float agg = ap[0] + ap[1];
        float hn  = g_lin[(size_t)r * HH + n] + agg;  // Uh + agg
        g_hnew[(size_t)r * HH + n] = hn;
        hs += (double)hn; hq += (double)hn * (double)hn;
    }
    hs = blk_red(hs, sb);
    hq = blk_red(hq, sb);
    if (tid == 0) {
        double mean = hs / (double)ROWS_H;
        double var  = hq / (double)ROWS_H - mean * mean;
        float rstd  = (float)(1.0 / sqrt(var + (double)EPS));
        float sc    = gamma_h[n] * rstd;
        sbroad[0]   = sc;
        sbroad[1]   = beta_h[n] - (float)mean * sc;
    }
    __syncthreads();
    float sc = sbroad[0], sh = sbroad[1];
    for (int r = tid; r < ROWS_H; r += 256) {
        float v = fmaf(g_hnew[(size_t)r * HH + n], sc, sh);
        out_h[(size_t)r * HH + n] = h_in[(size_t)r * HH + n] + fmaxf(v, 0.f);
    }
}

// ---------------- K3: e epilogue ----------------
__global__ void k_epi(const float* __restrict__ e_in, float* __restrict__ out_e) {
    int tid = threadIdx.x;
    const float4* en4 = (const float4*)g_enew;
    const float4* ei4 = (const float4*)e_in;
    const float4* sc4 = (const float4*)g_scaleE;
    const float4* sh4 = (const float4*)g_shiftE;
    float4* out4 = (float4*)out_e;
#pragma unroll
    for (int it = 0; it < 4; it++) {
        size_t f = (size_t)blockIdx.x * 1024 + it * 256 + tid;
        int c = (int)(f & 31);
        float4 sc = __ldg(&sc4[c]);
        float4 sh = __ldg(&sh4[c]);
        float4 x  = en4[f];
        float4 ei = ei4[f];
        float4 o;
        o.x = ei.x + fmaxf(fmaf(x.x, sc.x, sh.x), 0.f);
        o.y = ei.y + fmaxf(fmaf(x.y, sc.y, sh.y), 0.f);
        o.z = ei.z + fmaxf(fmaf(x.z, sc.z, sh.z), 0.f);
        o.w = ei.w + fmaxf(fmaf(x.w, sc.w, sh.w), 0.f);
        out4[f] = o;
    }
}

extern "C" void kernel_launch(void* const* d_in, const int* in_sizes, int n_in,
                              void* d_out, int out_size) {
    (void)in_sizes; (void)n_in; (void)out_size;
    const float* h  = (const float*)d_in[0];
    const float* e  = (const float*)d_in[1];
    const float* Uw = (const float*)d_in[3];
    const float* Ub = (const float*)d_in[4];
    const float* Vw = (const float*)d_in[5];
    const float* Vb = (const float*)d_in[6];
    const float* Aw = (const float*)d_in[7];
    const float* Ab = (const float*)d_in[8];
    const float* Bw = (const float*)d_in[9];
    const float* Bb = (const float*)d_in[10];
    const float* Cw = (const float*)d_in[11];
    const float* Cb = (const float*)d_in[12];
    const float* gh = (const float*)d_in[13];
    const float* bh = (const float*)d_in[14];
    const float* ge = (const float*)d_in[15];
    const float* be = (const float*)d_in[16];
    float* out = (float*)d_out;   // [h_out (131072) | e_out (33554432)]

    cudaFuncSetAttribute(k_lin,  cudaFuncAttributeMaxDynamicSharedMemorySize, SMEM_LIN);
    cudaFuncSetAttribute(k_main, cudaFuncAttributeMaxDynamicSharedMemorySize, SM_TOTAL);

    k_lin<<<dim3(ROWS_H / 64, 5), 256, SMEM_LIN>>>(h, Uw, Ub, Vw, Vb, Aw, Ab, Bw, Bb, Cw);
    k_main<<<NBLK2, 256, SM_TOTAL>>>(e, Cb);
    k_finalize<<<HH, 256>>>(h, gh, bh, ge, be, out);
    k_epi<<<ROWS_E * HH / 4096, 256>>>(e, out + ROWS_H * HH);
}